// round 2
// baseline (speedup 1.0000x reference)
#include <cuda_runtime.h>
#include <cuda_bf16.h>

// Problem constants
#define N_NODES 50000
#define N_EDGES 800000
#define IN_F    128
#define OUT_F   64

// ---------------------------------------------------------------------------
// Device scratch (no allocations allowed)
// ---------------------------------------------------------------------------
__device__ int   g_row_cnt[N_NODES];          // histogram, then scatter cursor
__device__ int   g_row_ptr[N_NODES + 1];      // CSR row pointers
__device__ int   g_col_sorted[N_EDGES];       // CSR col indices
__device__ float g_attr_sorted[N_EDGES];      // CSR edge weights
__device__ float g_buf0[N_NODES * OUT_F];     // ping
__device__ float g_buf1[N_NODES * OUT_F];     // pong

// ---------------------------------------------------------------------------
// 1) zero histogram counters
// ---------------------------------------------------------------------------
__global__ void zero_cnt_kernel() {
    int i = blockIdx.x * blockDim.x + threadIdx.x;
    if (i < N_NODES) g_row_cnt[i] = 0;
}

// ---------------------------------------------------------------------------
// 2) histogram of destination rows (int atomics, cheap)
//    edge_index is int32 (JAX default x64-disabled downcasts int64 -> int32).
// ---------------------------------------------------------------------------
__global__ void hist_kernel(const int* __restrict__ ei) {
    int e = blockIdx.x * blockDim.x + threadIdx.x;
    if (e < N_EDGES) {
        int row = ei[e];
        if (row >= 0 && row < N_NODES)
            atomicAdd(&g_row_cnt[row], 1);
    }
}

// ---------------------------------------------------------------------------
// 3) exclusive scan over 50000 counters, single block of 1024 threads.
//    Writes g_row_ptr and re-initializes g_row_cnt as scatter cursor.
// ---------------------------------------------------------------------------
__global__ void scan_kernel() {
    __shared__ int sm[1024];
    const int CH = (N_NODES + 1023) / 1024;   // 49
    int t = threadIdx.x;
    int base = t * CH;

    int s = 0;
    for (int j = 0; j < CH; j++) {
        int i = base + j;
        if (i < N_NODES) s += g_row_cnt[i];
    }
    sm[t] = s;
    __syncthreads();

    // Hillis-Steele inclusive scan
    int v = s;
    for (int off = 1; off < 1024; off <<= 1) {
        int add = (t >= off) ? sm[t - off] : 0;
        __syncthreads();
        v += add;
        sm[t] = v;
        __syncthreads();
    }
    int run = v - s;  // exclusive prefix for this chunk

    for (int j = 0; j < CH; j++) {
        int i = base + j;
        if (i < N_NODES) {
            int c = g_row_cnt[i];
            g_row_ptr[i] = run;
            g_row_cnt[i] = run;   // cursor for scatter
            run += c;
        }
    }
    if (t == 0) g_row_ptr[N_NODES] = N_EDGES;
}

// ---------------------------------------------------------------------------
// 4) scatter edges into CSR order
// ---------------------------------------------------------------------------
__global__ void scatter_kernel(const int* __restrict__ ei,
                               const float* __restrict__ attr) {
    int e = blockIdx.x * blockDim.x + threadIdx.x;
    if (e < N_EDGES) {
        int row = ei[e];
        int col = ei[N_EDGES + e];
        if (row >= 0 && row < N_NODES && col >= 0 && col < N_NODES) {
            int pos = atomicAdd(&g_row_cnt[row], 1);
            g_col_sorted[pos]  = col;
            g_attr_sorted[pos] = attr[e];
        }
    }
}

// ---------------------------------------------------------------------------
// 5) GEMM: out[n,o] = sum_k x[n,k] * W[o,k] + b[o]
//    Block = 256 threads, tile 64 rows x 64 outs. W transposed in smem.
//    Thread computes 4 rows x 4 outs with float4 k-steps.
// ---------------------------------------------------------------------------
__global__ __launch_bounds__(256, 4)
void gemm_kernel(const float* __restrict__ x,
                 const float* __restrict__ W,
                 const float* __restrict__ b,
                 float* __restrict__ out) {
    __shared__ float Ws[IN_F * 68];   // transposed, padded row stride 68

    // Load W (64x128) transposed into Ws[k*68 + o], coalesced global reads.
    for (int idx = threadIdx.x; idx < OUT_F * IN_F; idx += 256) {
        int o = idx >> 7;       // 0..63
        int k = idx & 127;      // 0..127
        Ws[k * 68 + o] = W[idx];
    }
    __syncthreads();

    int rg = threadIdx.x >> 4;   // 0..15 -> 4 rows each
    int og = threadIdx.x & 15;   // 0..15 -> 4 outs each
    int row0 = blockIdx.x * 64 + rg * 4;

    float acc[4][4];
#pragma unroll
    for (int i = 0; i < 4; i++)
#pragma unroll
        for (int j = 0; j < 4; j++) acc[i][j] = 0.0f;

    // Clamp rows for loads (store is guarded); avoids branches in hot loop.
    int r[4];
#pragma unroll
    for (int i = 0; i < 4; i++) {
        int rr = row0 + i;
        r[i] = rr < N_NODES ? rr : N_NODES - 1;
    }

    for (int k = 0; k < IN_F; k += 4) {
        float4 wv[4];
#pragma unroll
        for (int kk = 0; kk < 4; kk++)
            wv[kk] = *(const float4*)&Ws[(k + kk) * 68 + og * 4];
#pragma unroll
        for (int i = 0; i < 4; i++) {
            float4 xv = __ldg((const float4*)&x[r[i] * IN_F + k]);
            acc[i][0] += xv.x * wv[0].x; acc[i][1] += xv.x * wv[0].y;
            acc[i][2] += xv.x * wv[0].z; acc[i][3] += xv.x * wv[0].w;
            acc[i][0] += xv.y * wv[1].x; acc[i][1] += xv.y * wv[1].y;
            acc[i][2] += xv.y * wv[1].z; acc[i][3] += xv.y * wv[1].w;
            acc[i][0] += xv.z * wv[2].x; acc[i][1] += xv.z * wv[2].y;
            acc[i][2] += xv.z * wv[2].z; acc[i][3] += xv.z * wv[2].w;
            acc[i][0] += xv.w * wv[3].x; acc[i][1] += xv.w * wv[3].y;
            acc[i][2] += xv.w * wv[3].z; acc[i][3] += xv.w * wv[3].w;
        }
    }

    float4 bias = __ldg((const float4*)&b[og * 4]);
#pragma unroll
    for (int i = 0; i < 4; i++) {
        int rr = row0 + i;
        if (rr < N_NODES) {
            float4 o4;
            o4.x = acc[i][0] + bias.x;
            o4.y = acc[i][1] + bias.y;
            o4.z = acc[i][2] + bias.z;
            o4.w = acc[i][3] + bias.w;
            *(float4*)&out[rr * OUT_F + og * 4] = o4;
        }
    }
}

// ---------------------------------------------------------------------------
// 6) SPMM (CSR, warp per row): out[r,:] = sum_e attr[e] * in[col[e],:]
//    Lane handles 2 features (float2): 32 lanes x 2 = 64 features.
// ---------------------------------------------------------------------------
__global__ __launch_bounds__(256, 8)
void spmm_kernel(const float* __restrict__ in, float* __restrict__ out) {
    int warp = (blockIdx.x * blockDim.x + threadIdx.x) >> 5;
    int lane = threadIdx.x & 31;
    if (warp >= N_NODES) return;

    int s = g_row_ptr[warp];
    int e = g_row_ptr[warp + 1];

    const float2* inp = (const float2*)in;
    float2 acc = make_float2(0.0f, 0.0f);

    for (int i = s; i < e; i++) {
        int   c = __ldg(&g_col_sorted[i]);      // uniform -> broadcast
        float a = __ldg(&g_attr_sorted[i]);     // uniform -> broadcast
        float2 v = __ldg(&inp[c * 32 + lane]);  // coalesced 256B row gather
        acc.x += a * v.x;
        acc.y += a * v.y;
    }
    ((float2*)out)[warp * 32 + lane] = acc;
}

// ---------------------------------------------------------------------------
// launch
// ---------------------------------------------------------------------------
extern "C" void kernel_launch(void* const* d_in, const int* in_sizes, int n_in,
                              void* d_out, int out_size) {
    const float* x    = (const float*)d_in[0];
    const int*   ei   = (const int*)d_in[1];   // int32! (JAX x64 disabled)
    const float* attr = (const float*)d_in[2];
    const float* W    = (const float*)d_in[3];
    const float* b    = (const float*)d_in[4];
    float*       out  = (float*)d_out;

    // CSR build
    zero_cnt_kernel<<<(N_NODES + 255) / 256, 256>>>();
    hist_kernel<<<(N_EDGES + 255) / 256, 256>>>(ei);
    scan_kernel<<<1, 1024>>>();
    scatter_kernel<<<(N_EDGES + 255) / 256, 256>>>(ei, attr);

    // Resolve scratch pointers (host API, not a stream op — capture-legal).
    float *buf0, *buf1;
    cudaGetSymbolAddress((void**)&buf0, g_buf0);
    cudaGetSymbolAddress((void**)&buf1, g_buf1);

    // GEMM into buf0
    gemm_kernel<<<(N_NODES + 63) / 64, 256>>>(x, W, b, buf0);

    // 3 SPMM rounds: buf0 -> buf1 -> buf0 -> d_out
    int blocks = (N_NODES * 32 + 255) / 256;  // warp per row
    spmm_kernel<<<blocks, 256>>>(buf0, buf1);
    spmm_kernel<<<blocks, 256>>>(buf1, buf0);
    spmm_kernel<<<blocks, 256>>>(buf0, out);
}